// round 9
// baseline (speedup 1.0000x reference)
#include <cuda_runtime.h>
#include <math.h>
#include <stdint.h>

#define D 128
#define NLIT 8000
#define NCLA 16000
#define TSTEPS 8
#define MAX_NNZ (1 << 20)

// ---------------- persistent scratch (device globals; no allocs) -------------
__device__ float g_LCpre[NLIT * D];
__device__ float g_Cmsg[NCLA * D];
__device__ float g_Cs[NCLA * D];
__device__ float g_hC[NCLA * D];
__device__ float g_CLpre[NCLA * D];
__device__ float g_Lmsg[NLIT * D];
__device__ float g_L[2][NLIT * D];
__device__ float g_hL[NLIT * D];
__device__ float g_gatesC[NCLA * 4 * D];
__device__ float g_gatesL[NLIT * 4 * D];

__device__ int g_nnz;
__device__ int g_pairs[MAX_NNZ];
__device__ int g_cntL[NLIT], g_cntC[NCLA];
__device__ int g_fillL[NLIT], g_fillC[NCLA];
__device__ int g_ptrL[NLIT + 1], g_ptrC[NCLA + 1];
__device__ int g_colL[MAX_NNZ];  // per-literal: clause indices
__device__ int g_colC[MAX_NNZ];  // per-clause: literal indices

// ---------------- CSR build ---------------------------------------------------
__global__ void k_reset() {
    int i = blockIdx.x * blockDim.x + threadIdx.x;
    if (i < NLIT) { g_cntL[i] = 0; g_fillL[i] = 0; }
    if (i < NCLA) { g_cntC[i] = 0; g_fillC[i] = 0; }
    if (i == 0) g_nnz = 0;
}

// Scan dense M once; warp-aggregated nnz allocation (one atomic per warp-step).
// Trip count divides exactly, so the ballot is warp-uniform.
__global__ void k_count(const float* __restrict__ M) {
    const int total4 = (NLIT * NCLA) / 4;  // 32M float4
    int stride = gridDim.x * blockDim.x;
    int lane = threadIdx.x & 31;
    for (int i = blockIdx.x * blockDim.x + threadIdx.x; i < total4; i += stride) {
        float4 v = ((const float4*)M)[i];
        int base = i << 2;
        float vals[4] = {v.x, v.y, v.z, v.w};
        #pragma unroll
        for (int jj = 0; jj < 4; jj++) {
            bool nz = (vals[jj] != 0.0f);
            unsigned m = __ballot_sync(0xffffffffu, nz);
            if (!m) continue;
            int ldr = __ffs(m) - 1;
            int basep = 0;
            if (lane == ldr) basep = atomicAdd(&g_nnz, __popc(m));
            basep = __shfl_sync(0xffffffffu, basep, ldr);
            if (nz) {
                int idx = base + jj;
                int l = idx / NCLA;
                int c = idx - l * NCLA;
                int p = basep + __popc(m & ((1u << lane) - 1u));
                if (p < MAX_NNZ) g_pairs[p] = idx;
                atomicAdd(&g_cntL[l], 1);
                atomicAdd(&g_cntC[c], 1);
            }
        }
    }
}

// single-block exclusive scan: ptr[0..n], ptr[n] = total
__global__ void k_scan(const int* __restrict__ cnt, int* __restrict__ ptr, int n) {
    __shared__ int sums[1024];
    int t = threadIdx.x;
    int chunk = (n + blockDim.x - 1) / blockDim.x;
    int start = t * chunk;
    int end = min(start + chunk, n);
    int s = 0;
    for (int i = start; i < end; i++) { ptr[i] = s; s += cnt[i]; }
    sums[t] = s;
    __syncthreads();
    for (int off = 1; off < 1024; off <<= 1) {
        int v = (t >= off) ? sums[t - off] : 0;
        __syncthreads();
        sums[t] += v;
        __syncthreads();
    }
    int base = (t == 0) ? 0 : sums[t - 1];
    for (int i = start; i < end; i++) ptr[i] += base;
    if (t == blockDim.x - 1) ptr[n] = sums[t];
}

__global__ void k_fill() {
    int nnz = g_nnz;
    if (nnz > MAX_NNZ) nnz = MAX_NNZ;
    int stride = gridDim.x * blockDim.x;
    for (int p = blockIdx.x * blockDim.x + threadIdx.x; p < nnz; p += stride) {
        int idx = g_pairs[p];
        int l = idx / NCLA;
        int c = idx - l * NCLA;
        int a = atomicAdd(&g_fillL[l], 1);
        g_colL[g_ptrL[l] + a] = c;
        int b = atomicAdd(&g_fillC[c], 1);
        g_colC[g_ptrC[c] + b] = l;
    }
}

// ---------------- SpMM: warp per row, float4 lanes ---------------------------
__global__ void __launch_bounds__(128) k_spmm(
    const int* __restrict__ ptr, const int* __restrict__ col,
    const float* __restrict__ X, float* __restrict__ Y) {
    int r = blockIdx.x * 4 + (threadIdx.x >> 5);
    int lane = threadIdx.x & 31;
    int beg = ptr[r], end = ptr[r + 1];
    float4 acc = make_float4(0.f, 0.f, 0.f, 0.f);
    int j = beg;
    for (; j + 1 < end; j += 2) {
        float4 v0 = *((const float4*)(X + (size_t)col[j] * D) + lane);
        float4 v1 = *((const float4*)(X + (size_t)col[j + 1] * D) + lane);
        acc.x += v0.x + v1.x; acc.y += v0.y + v1.y;
        acc.z += v0.z + v1.z; acc.w += v0.w + v1.w;
    }
    if (j < end) {
        float4 v = *((const float4*)(X + (size_t)col[j] * D) + lane);
        acc.x += v.x; acc.y += v.y; acc.z += v.z; acc.w += v.w;
    }
    *((float4*)(Y + (size_t)r * D) + lane) = acc;
}

// ---------------- 6xTF32 GEMM, bias-free accumulation ------------------------
// Calibrated finding: chaining the mma C accumulator across K injects a BIASED
// (RZ-like) truncation error ~1e-6 per output (16 chained steps), which the
// 8-round recurrence amplifies ~2000x past the 1e-3 threshold. Fix:
//   * the dominant h*h product per K=8 chunk runs with C=0 and is Kahan-summed
//     into registers with round-to-nearest FADDs (unbiased),
//   * the 5 low-order products (<= 2^-11 magnitude) stay C-chained into a
//     separate accLo, where the truncation bias is scaled by 2^-11 (negligible).
// 3-way operand split: x = h + m + l (tf32 each, subs exact; rep err ~2^-33).
// Y[M,N] = sum_s A_s @ W_s^T (+ b1 + b2).
// Block tile 64x64, BK=16, 8 warps (2x4), warp tile 32x16, mma m16n8k8 tf32.
// Smem stride 20 floats: fragment loads 20g+q mod 32 all-distinct.
__device__ __forceinline__ float f2tf(float x) {
    uint32_t u;
    asm("cvt.rna.tf32.f32 %0, %1;" : "=r"(u) : "f"(x));
    return __uint_as_float(u);
}

#define GBK 16
#define SST 20

// chained-C accumulate (used only for low-order terms)
#define MMA_TF32(accp, a0, a1, a2, a3, bb0, bb1)                              \
    asm volatile(                                                             \
        "mma.sync.aligned.m16n8k8.row.col.f32.tf32.tf32.f32 "                 \
        "{%0,%1,%2,%3}, {%4,%5,%6,%7}, {%8,%9}, {%0,%1,%2,%3};\n"             \
        : "+f"((accp)[0]), "+f"((accp)[1]), "+f"((accp)[2]), "+f"((accp)[3])  \
        : "r"(a0), "r"(a1), "r"(a2), "r"(a3), "r"(bb0), "r"(bb1))

// C = 0 variant writing a fresh fragment (h*h term)
#define MMA_TF32_Z(outp, a0, a1, a2, a3, bb0, bb1)                            \
    asm volatile(                                                             \
        "mma.sync.aligned.m16n8k8.row.col.f32.tf32.tf32.f32 "                 \
        "{%0,%1,%2,%3}, {%4,%5,%6,%7}, {%8,%9}, {%10,%10,%10,%10};\n"         \
        : "=f"((outp)[0]), "=f"((outp)[1]), "=f"((outp)[2]), "=f"((outp)[3])  \
        : "r"(a0), "r"(a1), "r"(a2), "r"(a3), "r"(bb0), "r"(bb1), "f"(0.0f))

__global__ void __launch_bounds__(256) k_gemm_6xtf32(
    const float* __restrict__ A0, const float* __restrict__ W0, int ws0,
    const float* __restrict__ A1, const float* __restrict__ W1, int ws1,
    const float* __restrict__ A2, const float* __restrict__ W2, int ws2,
    const float* __restrict__ b1, const float* __restrict__ b2,
    float* __restrict__ Y, int N) {
    __shared__ float As[3][64][SST];  // [h/m/l][row][k]
    __shared__ float Bs[3][64][SST];

    int m0 = blockIdx.y * 64, n0 = blockIdx.x * 64;
    int t = threadIdx.x;
    int lane = t & 31;
    int warp = t >> 5;
    int wm = (warp >> 2) * 32;  // 2 warp-rows
    int wn = (warp & 3) * 16;   // 4 warp-cols
    int g = lane >> 2;          // groupID 0..7
    int q = lane & 3;           // threadID-in-group 0..3

    int arow = t >> 2;          // 0..63
    int ak = (t & 3) * 4;       // 0,4,8,12

    float accHi[2][2][4], comp[2][2][4], accLo[2][2][4];
    #pragma unroll
    for (int a = 0; a < 2; a++)
        #pragma unroll
        for (int b = 0; b < 2; b++)
            #pragma unroll
            for (int cidx = 0; cidx < 4; cidx++) {
                accHi[a][b][cidx] = 0.0f;
                comp[a][b][cidx] = 0.0f;
                accLo[a][b][cidx] = 0.0f;
            }

    const float* Aseg[3] = {A0, A1, A2};
    const float* Wseg[3] = {W0, W1, W2};
    int wss[3] = {ws0, ws1, ws2};

    #pragma unroll 1
    for (int s = 0; s < 3; s++) {
        const float* A = Aseg[s];
        if (!A) break;
        const float* W = Wseg[s];
        int ws = wss[s];
        #pragma unroll 1
        for (int k0 = 0; k0 < 128; k0 += GBK) {
            float av[4], wv[4];
            *(float4*)&av[0] = *(const float4*)(A + (size_t)(m0 + arow) * 128 + k0 + ak);
            *(float4*)&wv[0] = *(const float4*)(W + (size_t)(n0 + arow) * ws + k0 + ak);
            __syncthreads();
            {
                float h[4], m[4], l[4];
                #pragma unroll
                for (int i = 0; i < 4; i++) {
                    h[i] = f2tf(av[i]);
                    float r1 = av[i] - h[i];
                    m[i] = f2tf(r1);
                    l[i] = f2tf(r1 - m[i]);
                }
                *(float4*)&As[0][arow][ak] = *(float4*)&h[0];
                *(float4*)&As[1][arow][ak] = *(float4*)&m[0];
                *(float4*)&As[2][arow][ak] = *(float4*)&l[0];
                #pragma unroll
                for (int i = 0; i < 4; i++) {
                    h[i] = f2tf(wv[i]);
                    float r1 = wv[i] - h[i];
                    m[i] = f2tf(r1);
                    l[i] = f2tf(r1 - m[i]);
                }
                *(float4*)&Bs[0][arow][ak] = *(float4*)&h[0];
                *(float4*)&Bs[1][arow][ak] = *(float4*)&m[0];
                *(float4*)&Bs[2][arow][ak] = *(float4*)&l[0];
            }
            __syncthreads();
            #pragma unroll
            for (int kk = 0; kk < GBK; kk += 8) {
                uint32_t af[3][2][4], bf[3][2][2];
                #pragma unroll
                for (int pl = 0; pl < 3; pl++) {
                    #pragma unroll
                    for (int mt = 0; mt < 2; mt++) {
                        int m_ = wm + mt * 16;
                        af[pl][mt][0] = __float_as_uint(As[pl][m_ + g][kk + q]);
                        af[pl][mt][1] = __float_as_uint(As[pl][m_ + g + 8][kk + q]);
                        af[pl][mt][2] = __float_as_uint(As[pl][m_ + g][kk + q + 4]);
                        af[pl][mt][3] = __float_as_uint(As[pl][m_ + g + 8][kk + q + 4]);
                    }
                    #pragma unroll
                    for (int nt = 0; nt < 2; nt++) {
                        int n_ = wn + nt * 8;
                        bf[pl][nt][0] = __float_as_uint(Bs[pl][n_ + g][kk + q]);
                        bf[pl][nt][1] = __float_as_uint(Bs[pl][n_ + g][kk + q + 4]);
                    }
                }
                #pragma unroll
                for (int mt = 0; mt < 2; mt++)
                    #pragma unroll
                    for (int nt = 0; nt < 2; nt++) {
                        // low-order terms: C-chained (bias scaled by <=2^-11)
                        MMA_TF32(accLo[mt][nt], af[2][mt][0], af[2][mt][1], af[2][mt][2],
                                 af[2][mt][3], bf[0][nt][0], bf[0][nt][1]);  // l*h
                        MMA_TF32(accLo[mt][nt], af[1][mt][0], af[1][mt][1], af[1][mt][2],
                                 af[1][mt][3], bf[1][nt][0], bf[1][nt][1]);  // m*m
                        MMA_TF32(accLo[mt][nt], af[0][mt][0], af[0][mt][1], af[0][mt][2],
                                 af[0][mt][3], bf[2][nt][0], bf[2][nt][1]);  // h*l
                        MMA_TF32(accLo[mt][nt], af[1][mt][0], af[1][mt][1], af[1][mt][2],
                                 af[1][mt][3], bf[0][nt][0], bf[0][nt][1]);  // m*h
                        MMA_TF32(accLo[mt][nt], af[0][mt][0], af[0][mt][1], af[0][mt][2],
                                 af[0][mt][3], bf[1][nt][0], bf[1][nt][1]);  // h*m
                        // dominant h*h: fresh C=0 fragment, Kahan into registers
                        float tmp[4];
                        MMA_TF32_Z(tmp, af[0][mt][0], af[0][mt][1], af[0][mt][2],
                                   af[0][mt][3], bf[0][nt][0], bf[0][nt][1]);
                        #pragma unroll
                        for (int i = 0; i < 4; i++) {
                            float y = tmp[i] - comp[mt][nt][i];
                            float tsum = accHi[mt][nt][i] + y;
                            comp[mt][nt][i] = (tsum - accHi[mt][nt][i]) - y;
                            accHi[mt][nt][i] = tsum;
                        }
                    }
            }
        }
    }

    #pragma unroll
    for (int mt = 0; mt < 2; mt++)
        #pragma unroll
        for (int nt = 0; nt < 2; nt++) {
            int r0 = m0 + wm + mt * 16 + g;
            int r1 = r0 + 8;
            int c = n0 + wn + nt * 8 + 2 * q;
            float bs0 = (b1 ? b1[c] : 0.f) + (b2 ? b2[c] : 0.f);
            float bs1 = (b1 ? b1[c + 1] : 0.f) + (b2 ? b2[c + 1] : 0.f);
            float o0 = accHi[mt][nt][0] + (accLo[mt][nt][0] - comp[mt][nt][0]);
            float o1 = accHi[mt][nt][1] + (accLo[mt][nt][1] - comp[mt][nt][1]);
            float o2 = accHi[mt][nt][2] + (accLo[mt][nt][2] - comp[mt][nt][2]);
            float o3 = accHi[mt][nt][3] + (accLo[mt][nt][3] - comp[mt][nt][3]);
            Y[(size_t)r0 * N + c]     = o0 + bs0;
            Y[(size_t)r0 * N + c + 1] = o1 + bs1;
            Y[(size_t)r1 * N + c]     = o2 + bs0;
            Y[(size_t)r1 * N + c + 1] = o3 + bs1;
        }
}

// ---------------- LSTM pointwise ---------------------------------------------
__device__ __forceinline__ float sigm(float x) { return 1.0f / (1.0f + expf(-x)); }

// gate order (torch LSTM): i, f, g, o.  c and h come from the same buffer
// (reference carries c_new as both h and c of the next round).
__global__ void k_lstm(const float* __restrict__ gates, const float* __restrict__ c_old,
                       float* __restrict__ h_out, float* __restrict__ c_out, int rows) {
    int i = blockIdx.x * blockDim.x + threadIdx.x;
    if (i >= rows * D) return;
    int r = i / D, d = i - r * D;
    const float* gp = gates + (size_t)r * 4 * D;
    float gi = gp[d], gf = gp[D + d], gg = gp[2 * D + d], go = gp[3 * D + d];
    float c = c_old[i];
    float cn = sigm(gf) * c + sigm(gi) * tanhf(gg);
    float hn = sigm(go) * tanhf(cn);
    c_out[i] = cn;
    h_out[i] = hn;
}

// ---------------- host driver ------------------------------------------------
extern "C" void kernel_launch(void* const* d_in, const int* in_sizes, int n_in,
                              void* d_out, int out_size) {
    const float* L_state  = (const float*)d_in[0];
    const float* hidden_L = (const float*)d_in[2];
    const float* hidden_C = (const float*)d_in[3];
    const float* Mmat     = (const float*)d_in[4];
    int o = (n_in >= 18) ? 6 : 5;  // skip scalar n_vars if present
    const float* W_lc  = (const float*)d_in[o + 0];
    const float* b_lc  = (const float*)d_in[o + 1];
    const float* W_cl  = (const float*)d_in[o + 2];
    const float* b_cl  = (const float*)d_in[o + 3];
    const float* Wih_C = (const float*)d_in[o + 4];
    const float* Whh_C = (const float*)d_in[o + 5];
    const float* bih_C = (const float*)d_in[o + 6];
    const float* bhh_C = (const float*)d_in[o + 7];
    const float* Wih_L = (const float*)d_in[o + 8];
    const float* Whh_L = (const float*)d_in[o + 9];
    const float* bih_L = (const float*)d_in[o + 10];
    const float* bhh_L = (const float*)d_in[o + 11];

    void* p;
    cudaGetSymbolAddress(&p, g_L);      float* Lbuf   = (float*)p;
    cudaGetSymbolAddress(&p, g_hL);     float* hL     = (float*)p;
    cudaGetSymbolAddress(&p, g_hC);     float* hC     = (float*)p;
    cudaGetSymbolAddress(&p, g_LCpre);  float* LCpre  = (float*)p;
    cudaGetSymbolAddress(&p, g_Cmsg);   float* Cmsg   = (float*)p;
    cudaGetSymbolAddress(&p, g_Cs);     float* Cs     = (float*)p;
    cudaGetSymbolAddress(&p, g_CLpre);  float* CLpre  = (float*)p;
    cudaGetSymbolAddress(&p, g_Lmsg);   float* Lmsg   = (float*)p;
    cudaGetSymbolAddress(&p, g_gatesC); float* gatesC = (float*)p;
    cudaGetSymbolAddress(&p, g_gatesL); float* gatesL = (float*)p;
    cudaGetSymbolAddress(&p, g_ptrL);   int* ptrL = (int*)p;
    cudaGetSymbolAddress(&p, g_ptrC);   int* ptrC = (int*)p;
    cudaGetSymbolAddress(&p, g_colL);   int* colL = (int*)p;
    cudaGetSymbolAddress(&p, g_colC);   int* colC = (int*)p;
    cudaGetSymbolAddress(&p, g_cntL);   int* cntL = (int*)p;
    cudaGetSymbolAddress(&p, g_cntC);   int* cntC = (int*)p;

    // ---- CSR build (redone every launch; no caching allowed) ----
    k_reset<<<(NCLA + 255) / 256, 256>>>();
    k_count<<<2048, 256>>>(Mmat);
    k_scan<<<1, 1024>>>(cntL, ptrL, NLIT);
    k_scan<<<1, 1024>>>(cntC, ptrC, NCLA);
    k_fill<<<512, 256>>>();

    // ---- state init ----
    cudaMemcpyAsync(hC, hidden_C, sizeof(float) * NCLA * D, cudaMemcpyDeviceToDevice);
    cudaMemcpyAsync(hL, hidden_L, sizeof(float) * NLIT * D, cudaMemcpyDeviceToDevice);

    // ---- T message-passing rounds ----
    for (int r = 0; r < TSTEPS; r++) {
        const float* Lcur = (r == 0) ? L_state : (Lbuf + (size_t)(r & 1) * NLIT * D);
        float* Lnext = (r == TSTEPS - 1) ? (float*)d_out
                                         : (Lbuf + (size_t)((r + 1) & 1) * NLIT * D);

        // LC_pre = L @ W_lc^T + b_lc
        k_gemm_6xtf32<<<dim3(D / 64, NLIT / 64), 256>>>(
            Lcur, W_lc, D, nullptr, nullptr, 0, nullptr, nullptr, 0,
            b_lc, nullptr, LCpre, D);
        // LC_msgs = M^T @ LC_pre
        k_spmm<<<NCLA / 4, 128>>>(ptrC, colC, LCpre, Cmsg);
        // C gates = Cmsg @ Wih_C^T + hC @ Whh_C^T + bih + bhh
        k_gemm_6xtf32<<<dim3(4 * D / 64, NCLA / 64), 256>>>(
            Cmsg, Wih_C, D, hC, Whh_C, D, nullptr, nullptr, 0,
            bih_C, bhh_C, gatesC, 4 * D);
        k_lstm<<<(NCLA * D + 255) / 256, 256>>>(gatesC, hC, Cs, hC, NCLA);
        // CL_pre = Cs @ W_cl^T + b_cl
        k_gemm_6xtf32<<<dim3(D / 64, NCLA / 64), 256>>>(
            Cs, W_cl, D, nullptr, nullptr, 0, nullptr, nullptr, 0,
            b_cl, nullptr, CLpre, D);
        // CL_msgs = M @ CL_pre
        k_spmm<<<NLIT / 4, 128>>>(ptrL, colL, CLpre, Lmsg);
        // L gates = [Lmsg | Lcur] @ Wih_L^T + hL @ Whh_L^T + biases  (concat fused)
        k_gemm_6xtf32<<<dim3(4 * D / 64, NLIT / 64), 256>>>(
            Lmsg, Wih_L, 2 * D, Lcur, Wih_L + D, 2 * D, hL, Whh_L, D,
            bih_L, bhh_L, gatesL, 4 * D);
        k_lstm<<<(NLIT * D + 255) / 256, 256>>>(gatesL, hL, Lnext, hL, NLIT);
    }
}

// round 10
// speedup vs baseline: 1.4007x; 1.4007x over previous
#include <cuda_runtime.h>
#include <math.h>
#include <stdint.h>

#define D 128
#define NLIT 8000
#define NCLA 16000
#define TSTEPS 8
#define MAX_NNZ (1 << 20)

// ---------------- persistent scratch (device globals; no allocs) -------------
__device__ float g_LCpre[NLIT * D];
__device__ float g_Cmsg[NCLA * D];
__device__ float g_Cs[NCLA * D];
__device__ float g_hC[NCLA * D];
__device__ float g_CLpre[NCLA * D];
__device__ float g_Lmsg[NLIT * D];
__device__ float g_L[2][NLIT * D];
__device__ float g_hL[NLIT * D];
__device__ float g_gatesC[NCLA * 4 * D];
__device__ float g_gatesL[NLIT * 4 * D];

__device__ int g_nnz;
__device__ int g_pairs[MAX_NNZ];
__device__ int g_cntL[NLIT], g_cntC[NCLA];
__device__ int g_fillL[NLIT], g_fillC[NCLA];
__device__ int g_ptrL[NLIT + 1], g_ptrC[NCLA + 1];
__device__ int g_colL[MAX_NNZ];  // per-literal: clause indices
__device__ int g_colC[MAX_NNZ];  // per-clause: literal indices

// ---------------- CSR build ---------------------------------------------------
__global__ void k_reset() {
    int i = blockIdx.x * blockDim.x + threadIdx.x;
    if (i < NLIT) { g_cntL[i] = 0; g_fillL[i] = 0; }
    if (i < NCLA) { g_cntC[i] = 0; g_fillC[i] = 0; }
    if (i == 0) g_nnz = 0;
}

// Scan dense M once; warp-aggregated nnz allocation (one atomic per warp-step).
// Trip count divides exactly, so the ballot is warp-uniform.
__global__ void k_count(const float* __restrict__ M) {
    const int total4 = (NLIT * NCLA) / 4;  // 32M float4
    int stride = gridDim.x * blockDim.x;
    int lane = threadIdx.x & 31;
    for (int i = blockIdx.x * blockDim.x + threadIdx.x; i < total4; i += stride) {
        float4 v = ((const float4*)M)[i];
        int base = i << 2;
        float vals[4] = {v.x, v.y, v.z, v.w};
        #pragma unroll
        for (int jj = 0; jj < 4; jj++) {
            bool nz = (vals[jj] != 0.0f);
            unsigned m = __ballot_sync(0xffffffffu, nz);
            if (!m) continue;
            int ldr = __ffs(m) - 1;
            int basep = 0;
            if (lane == ldr) basep = atomicAdd(&g_nnz, __popc(m));
            basep = __shfl_sync(0xffffffffu, basep, ldr);
            if (nz) {
                int idx = base + jj;
                int l = idx / NCLA;
                int c = idx - l * NCLA;
                int p = basep + __popc(m & ((1u << lane) - 1u));
                if (p < MAX_NNZ) g_pairs[p] = idx;
                atomicAdd(&g_cntL[l], 1);
                atomicAdd(&g_cntC[c], 1);
            }
        }
    }
}

// single-block exclusive scan: ptr[0..n], ptr[n] = total
__global__ void k_scan(const int* __restrict__ cnt, int* __restrict__ ptr, int n) {
    __shared__ int sums[1024];
    int t = threadIdx.x;
    int chunk = (n + blockDim.x - 1) / blockDim.x;
    int start = t * chunk;
    int end = min(start + chunk, n);
    int s = 0;
    for (int i = start; i < end; i++) { ptr[i] = s; s += cnt[i]; }
    sums[t] = s;
    __syncthreads();
    for (int off = 1; off < 1024; off <<= 1) {
        int v = (t >= off) ? sums[t - off] : 0;
        __syncthreads();
        sums[t] += v;
        __syncthreads();
    }
    int base = (t == 0) ? 0 : sums[t - 1];
    for (int i = start; i < end; i++) ptr[i] += base;
    if (t == blockDim.x - 1) ptr[n] = sums[t];
}

__global__ void k_fill() {
    int nnz = g_nnz;
    if (nnz > MAX_NNZ) nnz = MAX_NNZ;
    int stride = gridDim.x * blockDim.x;
    for (int p = blockIdx.x * blockDim.x + threadIdx.x; p < nnz; p += stride) {
        int idx = g_pairs[p];
        int l = idx / NCLA;
        int c = idx - l * NCLA;
        int a = atomicAdd(&g_fillL[l], 1);
        g_colL[g_ptrL[l] + a] = c;
        int b = atomicAdd(&g_fillC[c], 1);
        g_colC[g_ptrC[c] + b] = l;
    }
}

// ---------------- SpMM: warp per row, float4 lanes ---------------------------
__global__ void __launch_bounds__(128) k_spmm(
    const int* __restrict__ ptr, const int* __restrict__ col,
    const float* __restrict__ X, float* __restrict__ Y) {
    int r = blockIdx.x * 4 + (threadIdx.x >> 5);
    int lane = threadIdx.x & 31;
    int beg = ptr[r], end = ptr[r + 1];
    float4 acc = make_float4(0.f, 0.f, 0.f, 0.f);
    int j = beg;
    for (; j + 1 < end; j += 2) {
        float4 v0 = *((const float4*)(X + (size_t)col[j] * D) + lane);
        float4 v1 = *((const float4*)(X + (size_t)col[j + 1] * D) + lane);
        acc.x += v0.x + v1.x; acc.y += v0.y + v1.y;
        acc.z += v0.z + v1.z; acc.w += v0.w + v1.w;
    }
    if (j < end) {
        float4 v = *((const float4*)(X + (size_t)col[j] * D) + lane);
        acc.x += v.x; acc.y += v.y; acc.z += v.z; acc.w += v.w;
    }
    *((float4*)(Y + (size_t)r * D) + lane) = acc;
}

// ---------------- bf16x3 tensor-core GEMM (fp32-accurate) --------------------
// Validated-in-run findings this builds on:
//  * chained mma C accumulation injects a BIASED truncation error (~1e-6/output
//    over 16 steps) that the 8-round recurrence amplifies ~2000x -> fail.
//    Fix (R9, proven): dominant product uses C=0 fragments + register Kahan
//    (round-to-nearest FADDs, unbiased); low-order products stay C-chained
//    where the bias is scaled by their magnitude (<= 2^-8).
//  * operand representation: 3-way bf16 split x = h + m + l gives 24 effective
//    mantissa bits (= fp32). Kept products: h*h (Kahan), h*m, m*h, m*m, h*l,
//    l*h (chained). Dropped m*l, l*l ~ 2^-24 -> fp32-class.
// m16n8k16 bf16 does 2x the K per mma vs tf32 m16n8k8 -> half the mma count,
// half the fragment LDS, half the Kahan FADDs of the R9 kernel.
// Y[M,N] = sum_s A_s @ W_s^T (+ b1 + b2).
// Block tile 64x64, BK=16, 8 warps (2x4), warp tile 32x16.
// Smem holds packed bf16 k-pairs (u32); row stride 12 u32:
//   fragment loads hit addresses 12g+q (+4) mod 32, all distinct -> conflict-free.

#define GBK 16
#define SSTP 12

// split two fp32 into 3 packed bf16x2 planes (hi half = second element)
__device__ __forceinline__ void bf16_split2(float x0, float x1,
                                            uint32_t& hp, uint32_t& mp, uint32_t& lp) {
    asm("cvt.rn.bf16x2.f32 %0, %1, %2;" : "=r"(hp) : "f"(x1), "f"(x0));
    float h0 = __uint_as_float(hp << 16);
    float h1 = __uint_as_float(hp & 0xffff0000u);
    float r0 = x0 - h0;
    float r1 = x1 - h1;
    asm("cvt.rn.bf16x2.f32 %0, %1, %2;" : "=r"(mp) : "f"(r1), "f"(r0));
    float m0 = __uint_as_float(mp << 16);
    float m1 = __uint_as_float(mp & 0xffff0000u);
    float s0 = r0 - m0;
    float s1 = r1 - m1;
    asm("cvt.rn.bf16x2.f32 %0, %1, %2;" : "=r"(lp) : "f"(s1), "f"(s0));
}

// chained-C accumulate (low-order terms only)
#define MMA_BF16(accp, a0, a1, a2, a3, bb0, bb1)                              \
    asm volatile(                                                             \
        "mma.sync.aligned.m16n8k16.row.col.f32.bf16.bf16.f32 "                \
        "{%0,%1,%2,%3}, {%4,%5,%6,%7}, {%8,%9}, {%0,%1,%2,%3};\n"             \
        : "+f"((accp)[0]), "+f"((accp)[1]), "+f"((accp)[2]), "+f"((accp)[3])  \
        : "r"(a0), "r"(a1), "r"(a2), "r"(a3), "r"(bb0), "r"(bb1))

// C = 0 variant writing a fresh fragment (h*h term)
#define MMA_BF16_Z(outp, a0, a1, a2, a3, bb0, bb1)                            \
    asm volatile(                                                             \
        "mma.sync.aligned.m16n8k16.row.col.f32.bf16.bf16.f32 "                \
        "{%0,%1,%2,%3}, {%4,%5,%6,%7}, {%8,%9}, {%10,%10,%10,%10};\n"         \
        : "=f"((outp)[0]), "=f"((outp)[1]), "=f"((outp)[2]), "=f"((outp)[3])  \
        : "r"(a0), "r"(a1), "r"(a2), "r"(a3), "r"(bb0), "r"(bb1), "f"(0.0f))

__global__ void __launch_bounds__(256) k_gemm_bf16x3(
    const float* __restrict__ A0, const float* __restrict__ W0, int ws0,
    const float* __restrict__ A1, const float* __restrict__ W1, int ws1,
    const float* __restrict__ A2, const float* __restrict__ W2, int ws2,
    const float* __restrict__ b1, const float* __restrict__ b2,
    float* __restrict__ Y, int N) {
    __shared__ uint32_t As[3][64][SSTP];  // [h/m/l][row][k-pair]
    __shared__ uint32_t Bs[3][64][SSTP];

    int m0 = blockIdx.y * 64, n0 = blockIdx.x * 64;
    int t = threadIdx.x;
    int lane = t & 31;
    int warp = t >> 5;
    int wm = (warp >> 2) * 32;  // 2 warp-rows
    int wn = (warp & 3) * 16;   // 4 warp-cols
    int g = lane >> 2;          // groupID 0..7
    int q = lane & 3;           // threadID-in-group 0..3

    int arow = t >> 2;          // 0..63
    int ak = (t & 3) * 4;       // float offset 0,4,8,12
    int apk = (t & 3) * 2;      // pair offset 0,2,4,6

    float accHi[2][2][4], comp[2][2][4], accLo[2][2][4];
    #pragma unroll
    for (int a = 0; a < 2; a++)
        #pragma unroll
        for (int b = 0; b < 2; b++)
            #pragma unroll
            for (int cidx = 0; cidx < 4; cidx++) {
                accHi[a][b][cidx] = 0.0f;
                comp[a][b][cidx] = 0.0f;
                accLo[a][b][cidx] = 0.0f;
            }

    const float* Aseg[3] = {A0, A1, A2};
    const float* Wseg[3] = {W0, W1, W2};
    int wss[3] = {ws0, ws1, ws2};

    #pragma unroll 1
    for (int s = 0; s < 3; s++) {
        const float* A = Aseg[s];
        if (!A) break;
        const float* W = Wseg[s];
        int ws = wss[s];
        #pragma unroll 1
        for (int k0 = 0; k0 < 128; k0 += GBK) {
            float av[4], wv[4];
            *(float4*)&av[0] = *(const float4*)(A + (size_t)(m0 + arow) * 128 + k0 + ak);
            *(float4*)&wv[0] = *(const float4*)(W + (size_t)(n0 + arow) * ws + k0 + ak);
            __syncthreads();
            {
                uint32_t h0, m0p, l0, h1, m1p, l1;
                bf16_split2(av[0], av[1], h0, m0p, l0);
                bf16_split2(av[2], av[3], h1, m1p, l1);
                As[0][arow][apk] = h0;  As[0][arow][apk + 1] = h1;
                As[1][arow][apk] = m0p; As[1][arow][apk + 1] = m1p;
                As[2][arow][apk] = l0;  As[2][arow][apk + 1] = l1;
                bf16_split2(wv[0], wv[1], h0, m0p, l0);
                bf16_split2(wv[2], wv[3], h1, m1p, l1);
                Bs[0][arow][apk] = h0;  Bs[0][arow][apk + 1] = h1;
                Bs[1][arow][apk] = m0p; Bs[1][arow][apk + 1] = m1p;
                Bs[2][arow][apk] = l0;  Bs[2][arow][apk + 1] = l1;
            }
            __syncthreads();

            // one m16n8k16 step covers all 16 k of this tile
            uint32_t af[3][2][4], bf[3][2][2];
            #pragma unroll
            for (int pl = 0; pl < 3; pl++) {
                #pragma unroll
                for (int mt = 0; mt < 2; mt++) {
                    int m_ = wm + mt * 16;
                    af[pl][mt][0] = As[pl][m_ + g][q];
                    af[pl][mt][1] = As[pl][m_ + g + 8][q];
                    af[pl][mt][2] = As[pl][m_ + g][q + 4];
                    af[pl][mt][3] = As[pl][m_ + g + 8][q + 4];
                }
                #pragma unroll
                for (int nt = 0; nt < 2; nt++) {
                    int n_ = wn + nt * 8;
                    bf[pl][nt][0] = Bs[pl][n_ + g][q];
                    bf[pl][nt][1] = Bs[pl][n_ + g][q + 4];
                }
            }
            #pragma unroll
            for (int mt = 0; mt < 2; mt++)
                #pragma unroll
                for (int nt = 0; nt < 2; nt++) {
                    // low-order products: C-chained (bias scaled by <= 2^-8)
                    MMA_BF16(accLo[mt][nt], af[2][mt][0], af[2][mt][1], af[2][mt][2],
                             af[2][mt][3], bf[0][nt][0], bf[0][nt][1]);  // l*h
                    MMA_BF16(accLo[mt][nt], af[1][mt][0], af[1][mt][1], af[1][mt][2],
                             af[1][mt][3], bf[1][nt][0], bf[1][nt][1]);  // m*m
                    MMA_BF16(accLo[mt][nt], af[0][mt][0], af[0][mt][1], af[0][mt][2],
                             af[0][mt][3], bf[2][nt][0], bf[2][nt][1]);  // h*l
                    MMA_BF16(accLo[mt][nt], af[1][mt][0], af[1][mt][1], af[1][mt][2],
                             af[1][mt][3], bf[0][nt][0], bf[0][nt][1]);  // m*h
                    MMA_BF16(accLo[mt][nt], af[0][mt][0], af[0][mt][1], af[0][mt][2],
                             af[0][mt][3], bf[1][nt][0], bf[1][nt][1]);  // h*m
                    // dominant h*h: fresh C=0 fragment, Kahan into registers
                    float tmp[4];
                    MMA_BF16_Z(tmp, af[0][mt][0], af[0][mt][1], af[0][mt][2],
                               af[0][mt][3], bf[0][nt][0], bf[0][nt][1]);
                    #pragma unroll
                    for (int i = 0; i < 4; i++) {
                        float y = tmp[i] - comp[mt][nt][i];
                        float tsum = accHi[mt][nt][i] + y;
                        comp[mt][nt][i] = (tsum - accHi[mt][nt][i]) - y;
                        accHi[mt][nt][i] = tsum;
                    }
                }
        }
    }

    #pragma unroll
    for (int mt = 0; mt < 2; mt++)
        #pragma unroll
        for (int nt = 0; nt < 2; nt++) {
            int r0 = m0 + wm + mt * 16 + g;
            int r1 = r0 + 8;
            int c = n0 + wn + nt * 8 + 2 * q;
            float bs0 = (b1 ? b1[c] : 0.f) + (b2 ? b2[c] : 0.f);
            float bs1 = (b1 ? b1[c + 1] : 0.f) + (b2 ? b2[c + 1] : 0.f);
            float o0 = accHi[mt][nt][0] + (accLo[mt][nt][0] - comp[mt][nt][0]);
            float o1 = accHi[mt][nt][1] + (accLo[mt][nt][1] - comp[mt][nt][1]);
            float o2 = accHi[mt][nt][2] + (accLo[mt][nt][2] - comp[mt][nt][2]);
            float o3 = accHi[mt][nt][3] + (accLo[mt][nt][3] - comp[mt][nt][3]);
            Y[(size_t)r0 * N + c]     = o0 + bs0;
            Y[(size_t)r0 * N + c + 1] = o1 + bs1;
            Y[(size_t)r1 * N + c]     = o2 + bs0;
            Y[(size_t)r1 * N + c + 1] = o3 + bs1;
        }
}

// ---------------- LSTM pointwise ---------------------------------------------
__device__ __forceinline__ float sigm(float x) { return 1.0f / (1.0f + expf(-x)); }

// gate order (torch LSTM): i, f, g, o.  c and h come from the same buffer
// (reference carries c_new as both h and c of the next round).
__global__ void k_lstm(const float* __restrict__ gates, const float* __restrict__ c_old,
                       float* __restrict__ h_out, float* __restrict__ c_out, int rows) {
    int i = blockIdx.x * blockDim.x + threadIdx.x;
    if (i >= rows * D) return;
    int r = i / D, d = i - r * D;
    const float* gp = gates + (size_t)r * 4 * D;
    float gi = gp[d], gf = gp[D + d], gg = gp[2 * D + d], go = gp[3 * D + d];
    float c = c_old[i];
    float cn = sigm(gf) * c + sigm(gi) * tanhf(gg);
    float hn = sigm(go) * tanhf(cn);
    c_out[i] = cn;
    h_out[i] = hn;
}

// ---------------- host driver ------------------------------------------------
extern "C" void kernel_launch(void* const* d_in, const int* in_sizes, int n_in,
                              void* d_out, int out_size) {
    const float* L_state  = (const float*)d_in[0];
    const float* hidden_L = (const float*)d_in[2];
    const float* hidden_C = (const float*)d_in[3];
    const float* Mmat     = (const float*)d_in[4];
    int o = (n_in >= 18) ? 6 : 5;  // skip scalar n_vars if present
    const float* W_lc  = (const float*)d_in[o + 0];
    const float* b_lc  = (const float*)d_in[o + 1];
    const float* W_cl  = (const float*)d_in[o + 2];
    const float* b_cl  = (const float*)d_in[o + 3];
    const float* Wih_C = (const float*)d_in[o + 4];
    const float* Whh_C = (const float*)d_in[o + 5];
    const float* bih_C = (const float*)d_in[o + 6];
    const float* bhh_C = (const float*)d_in[o + 7];
    const float* Wih_L = (const float*)d_in[o + 8];
    const float* Whh_L = (const float*)d_in[o + 9];
    const float* bih_L = (const float*)d_in[o + 10];
    const float* bhh_L = (const float*)d_in[o + 11];

    void* p;
    cudaGetSymbolAddress(&p, g_L);      float* Lbuf   = (float*)p;
    cudaGetSymbolAddress(&p, g_hL);     float* hL     = (float*)p;
    cudaGetSymbolAddress(&p, g_hC);     float* hC     = (float*)p;
    cudaGetSymbolAddress(&p, g_LCpre);  float* LCpre  = (float*)p;
    cudaGetSymbolAddress(&p, g_Cmsg);   float* Cmsg   = (float*)p;
    cudaGetSymbolAddress(&p, g_Cs);     float* Cs     = (float*)p;
    cudaGetSymbolAddress(&p, g_CLpre);  float* CLpre  = (float*)p;
    cudaGetSymbolAddress(&p, g_Lmsg);   float* Lmsg   = (float*)p;
    cudaGetSymbolAddress(&p, g_gatesC); float* gatesC = (float*)p;
    cudaGetSymbolAddress(&p, g_gatesL); float* gatesL = (float*)p;
    cudaGetSymbolAddress(&p, g_ptrL);   int* ptrL = (int*)p;
    cudaGetSymbolAddress(&p, g_ptrC);   int* ptrC = (int*)p;
    cudaGetSymbolAddress(&p, g_colL);   int* colL = (int*)p;
    cudaGetSymbolAddress(&p, g_colC);   int* colC = (int*)p;
    cudaGetSymbolAddress(&p, g_cntL);   int* cntL = (int*)p;
    cudaGetSymbolAddress(&p, g_cntC);   int* cntC = (int*)p;

    // ---- CSR build (redone every launch; no caching allowed) ----
    k_reset<<<(NCLA + 255) / 256, 256>>>();
    k_count<<<2048, 256>>>(Mmat);
    k_scan<<<1, 1024>>>(cntL, ptrL, NLIT);
    k_scan<<<1, 1024>>>(cntC, ptrC, NCLA);
    k_fill<<<512, 256>>>();

    // ---- state init ----
    cudaMemcpyAsync(hC, hidden_C, sizeof(float) * NCLA * D, cudaMemcpyDeviceToDevice);
    cudaMemcpyAsync(hL, hidden_L, sizeof(float) * NLIT * D, cudaMemcpyDeviceToDevice);

    // ---- T message-passing rounds ----
    for (int r = 0; r < TSTEPS; r++) {
        const float* Lcur = (r == 0) ? L_state : (Lbuf + (size_t)(r & 1) * NLIT * D);
        float* Lnext = (r == TSTEPS - 1) ? (float*)d_out
                                         : (Lbuf + (size_t)((r + 1) & 1) * NLIT * D);

        // LC_pre = L @ W_lc^T + b_lc
        k_gemm_bf16x3<<<dim3(D / 64, NLIT / 64), 256>>>(
            Lcur, W_lc, D, nullptr, nullptr, 0, nullptr, nullptr, 0,
            b_lc, nullptr, LCpre, D);
        // LC_msgs = M^T @ LC_pre
        k_spmm<<<NCLA / 4, 128>>>(ptrC, colC, LCpre, Cmsg);
        // C gates = Cmsg @ Wih_C^T + hC @ Whh_C^T + bih + bhh
        k_gemm_bf16x3<<<dim3(4 * D / 64, NCLA / 64), 256>>>(
            Cmsg, Wih_C, D, hC, Whh_C, D, nullptr, nullptr, 0,
            bih_C, bhh_C, gatesC, 4 * D);
        k_lstm<<<(NCLA * D + 255) / 256, 256>>>(gatesC, hC, Cs, hC, NCLA);
        // CL_pre = Cs @ W_cl^T + b_cl
        k_gemm_bf16x3<<<dim3(D / 64, NCLA / 64), 256>>>(
            Cs, W_cl, D, nullptr, nullptr, 0, nullptr, nullptr, 0,
            b_cl, nullptr, CLpre, D);
        // CL_msgs = M @ CL_pre
        k_spmm<<<NLIT / 4, 128>>>(ptrL, colL, CLpre, Lmsg);
        // L gates = [Lmsg | Lcur] @ Wih_L^T + hL @ Whh_L^T + biases  (concat fused)
        k_gemm_bf16x3<<<dim3(4 * D / 64, NLIT / 64), 256>>>(
            Lmsg, Wih_L, 2 * D, Lcur, Wih_L + D, 2 * D, hL, Whh_L, D,
            bih_L, bhh_L, gatesL, 4 * D);
        k_lstm<<<(NLIT * D + 255) / 256, 256>>>(gatesL, hL, Lnext, hL, NLIT);
    }
}

// round 11
// speedup vs baseline: 1.4054x; 1.0034x over previous
#include <cuda_runtime.h>
#include <math.h>
#include <stdint.h>

#define D 128
#define NLIT 8000
#define NCLA 16000
#define TSTEPS 8
#define MAX_NNZ (1 << 20)

// ---------------- persistent scratch (device globals; no allocs) -------------
__device__ float g_LCpre[NLIT * D];
__device__ float g_hC[NCLA * D];
__device__ float g_CLpre[NCLA * D];
__device__ float g_hL[NLIT * D];
__device__ float g_gatesC[NCLA * 4 * D];
__device__ float g_gatesL[NLIT * 4 * D];

// bf16 plane buffers: layout [3][rows][K/2] u32 (plane stride = rows*K/2)
__device__ uint32_t g_pW_lc[3 * 128 * 64];
__device__ uint32_t g_pW_cl[3 * 128 * 64];
__device__ uint32_t g_pWih_C[3 * 512 * 64];
__device__ uint32_t g_pWhh_C[3 * 512 * 64];
__device__ uint32_t g_pWih_L[3 * 512 * 128];
__device__ uint32_t g_pWhh_L[3 * 512 * 64];
__device__ uint32_t g_pL[2][3 * NLIT * 64];
__device__ uint32_t g_phL[3 * NLIT * 64];
__device__ uint32_t g_pCmsg[3 * NCLA * 64];
__device__ uint32_t g_phC[3 * NCLA * 64];
__device__ uint32_t g_pCs[3 * NCLA * 64];
__device__ uint32_t g_pLmsg[3 * NLIT * 64];

__device__ int g_nnz;
__device__ int g_pairs[MAX_NNZ];
__device__ int g_cntL[NLIT], g_cntC[NCLA];
__device__ int g_fillL[NLIT], g_fillC[NCLA];
__device__ int g_ptrL[NLIT + 1], g_ptrC[NCLA + 1];
__device__ int g_colL[MAX_NNZ];
__device__ int g_colC[MAX_NNZ];

// split two fp32 into 3 packed bf16x2 planes (hi half = second element)
__device__ __forceinline__ void bf16_split2(float x0, float x1,
                                            uint32_t& hp, uint32_t& mp, uint32_t& lp) {
    asm("cvt.rn.bf16x2.f32 %0, %1, %2;" : "=r"(hp) : "f"(x1), "f"(x0));
    float h0 = __uint_as_float(hp << 16);
    float h1 = __uint_as_float(hp & 0xffff0000u);
    float r0 = x0 - h0;
    float r1 = x1 - h1;
    asm("cvt.rn.bf16x2.f32 %0, %1, %2;" : "=r"(mp) : "f"(r1), "f"(r0));
    float m0 = __uint_as_float(mp << 16);
    float m1 = __uint_as_float(mp & 0xffff0000u);
    float s0 = r0 - m0;
    float s1 = r1 - m1;
    asm("cvt.rn.bf16x2.f32 %0, %1, %2;" : "=r"(lp) : "f"(s1), "f"(s0));
}

// ---------------- CSR build ---------------------------------------------------
__global__ void k_reset() {
    int i = blockIdx.x * blockDim.x + threadIdx.x;
    if (i < NLIT) { g_cntL[i] = 0; g_fillL[i] = 0; }
    if (i < NCLA) { g_cntC[i] = 0; g_fillC[i] = 0; }
    if (i == 0) g_nnz = 0;
}

__global__ void k_count(const float* __restrict__ M) {
    const int total4 = (NLIT * NCLA) / 4;  // exact trip count -> warp-uniform ballot
    int stride = gridDim.x * blockDim.x;
    int lane = threadIdx.x & 31;
    for (int i = blockIdx.x * blockDim.x + threadIdx.x; i < total4; i += stride) {
        float4 v = ((const float4*)M)[i];
        int base = i << 2;
        float vals[4] = {v.x, v.y, v.z, v.w};
        #pragma unroll
        for (int jj = 0; jj < 4; jj++) {
            bool nz = (vals[jj] != 0.0f);
            unsigned m = __ballot_sync(0xffffffffu, nz);
            if (!m) continue;
            int ldr = __ffs(m) - 1;
            int basep = 0;
            if (lane == ldr) basep = atomicAdd(&g_nnz, __popc(m));
            basep = __shfl_sync(0xffffffffu, basep, ldr);
            if (nz) {
                int idx = base + jj;
                int l = idx / NCLA;
                int c = idx - l * NCLA;
                int p = basep + __popc(m & ((1u << lane) - 1u));
                if (p < MAX_NNZ) g_pairs[p] = idx;
                atomicAdd(&g_cntL[l], 1);
                atomicAdd(&g_cntC[c], 1);
            }
        }
    }
}

__global__ void k_scan(const int* __restrict__ cnt, int* __restrict__ ptr, int n) {
    __shared__ int sums[1024];
    int t = threadIdx.x;
    int chunk = (n + blockDim.x - 1) / blockDim.x;
    int start = t * chunk;
    int end = min(start + chunk, n);
    int s = 0;
    for (int i = start; i < end; i++) { ptr[i] = s; s += cnt[i]; }
    sums[t] = s;
    __syncthreads();
    for (int off = 1; off < 1024; off <<= 1) {
        int v = (t >= off) ? sums[t - off] : 0;
        __syncthreads();
        sums[t] += v;
        __syncthreads();
    }
    int base = (t == 0) ? 0 : sums[t - 1];
    for (int i = start; i < end; i++) ptr[i] += base;
    if (t == blockDim.x - 1) ptr[n] = sums[t];
}

__global__ void k_fill() {
    int nnz = g_nnz;
    if (nnz > MAX_NNZ) nnz = MAX_NNZ;
    int stride = gridDim.x * blockDim.x;
    for (int p = blockIdx.x * blockDim.x + threadIdx.x; p < nnz; p += stride) {
        int idx = g_pairs[p];
        int l = idx / NCLA;
        int c = idx - l * NCLA;
        int a = atomicAdd(&g_fillL[l], 1);
        g_colL[g_ptrL[l] + a] = c;
        int b = atomicAdd(&g_fillC[c], 1);
        g_colC[g_ptrC[c] + b] = l;
    }
}

// ---------------- generic fp32 -> 3-plane split (weights, round-0 L) ---------
__global__ void k_split(const float* __restrict__ X, uint32_t* __restrict__ planes,
                        int npairs, int planeStride) {
    int i = blockIdx.x * blockDim.x + threadIdx.x;
    if (i >= npairs) return;
    float x0 = X[2 * i], x1 = X[2 * i + 1];
    uint32_t h, m, l;
    bf16_split2(x0, x1, h, m, l);
    planes[i] = h;
    planes[planeStride + i] = m;
    planes[2 * planeStride + i] = l;
}

// ---------------- SpMM: warp per row, emits bf16 planes directly -------------
__global__ void __launch_bounds__(128) k_spmm_split(
    const int* __restrict__ ptr, const int* __restrict__ col,
    const float* __restrict__ X, uint32_t* __restrict__ planes, int planeStride) {
    int r = blockIdx.x * 4 + (threadIdx.x >> 5);
    int lane = threadIdx.x & 31;
    int beg = ptr[r], end = ptr[r + 1];
    float4 acc = make_float4(0.f, 0.f, 0.f, 0.f);
    int j = beg;
    for (; j + 1 < end; j += 2) {
        float4 v0 = *((const float4*)(X + (size_t)col[j] * D) + lane);
        float4 v1 = *((const float4*)(X + (size_t)col[j + 1] * D) + lane);
        acc.x += v0.x + v1.x; acc.y += v0.y + v1.y;
        acc.z += v0.z + v1.z; acc.w += v0.w + v1.w;
    }
    if (j < end) {
        float4 v = *((const float4*)(X + (size_t)col[j] * D) + lane);
        acc.x += v.x; acc.y += v.y; acc.z += v.z; acc.w += v.w;
    }
    uint32_t h0, m0, l0, h1, m1, l1;
    bf16_split2(acc.x, acc.y, h0, m0, l0);
    bf16_split2(acc.z, acc.w, h1, m1, l1);
    int o = r * 64 + lane * 2;
    planes[o] = h0;                    planes[o + 1] = h1;
    planes[planeStride + o] = m0;      planes[planeStride + o + 1] = m1;
    planes[2 * planeStride + o] = l0;  planes[2 * planeStride + o + 1] = l1;
}

// ---------------- LSTM pointwise, emits fp32 state + bf16 planes -------------
__device__ __forceinline__ float sigm(float x) { return 1.0f / (1.0f + expf(-x)); }

// gate order (torch): i, f, g, o. c and h come from the same buffer (reference
// carries c_new as both h and c of the next round). Each thread does 2 elems.
__global__ void k_lstm_split(const float* __restrict__ gates,
                             float* __restrict__ c_state,          // in/out fp32
                             float* __restrict__ h_fp32,           // optional
                             uint32_t* __restrict__ h_planes, int hPS,
                             uint32_t* __restrict__ c_planes, int cPS,
                             int rows) {
    int i = blockIdx.x * blockDim.x + threadIdx.x;  // pair index
    if (i >= rows * 64) return;
    int r = i >> 6, pr = i & 63;
    int d0 = pr * 2;
    const float* gp = gates + (size_t)r * 4 * D;
    float c0 = c_state[r * D + d0], c1 = c_state[r * D + d0 + 1];
    float cn0 = sigm(gp[D + d0]) * c0 + sigm(gp[d0]) * tanhf(gp[2 * D + d0]);
    float cn1 = sigm(gp[D + d0 + 1]) * c1 + sigm(gp[d0 + 1]) * tanhf(gp[2 * D + d0 + 1]);
    float hn0 = sigm(gp[3 * D + d0]) * tanhf(cn0);
    float hn1 = sigm(gp[3 * D + d0 + 1]) * tanhf(cn1);
    c_state[r * D + d0] = cn0;
    c_state[r * D + d0 + 1] = cn1;
    if (h_fp32) { h_fp32[r * D + d0] = hn0; h_fp32[r * D + d0 + 1] = hn1; }
    uint32_t h, m, l;
    bf16_split2(hn0, hn1, h, m, l);
    h_planes[i] = h; h_planes[hPS + i] = m; h_planes[2 * hPS + i] = l;
    bf16_split2(cn0, cn1, h, m, l);
    c_planes[i] = h; c_planes[cPS + i] = m; c_planes[2 * cPS + i] = l;
}

// ---------------- bf16x3 tensor-core GEMM on pre-split planes ----------------
// Numerics identical to the validated R10 kernel: dominant h*h per k16 step via
// C=0 fragments + register Kahan (unbiased RN); 5 low-order products C-chained
// into accLo (bias scaled <= 2^-8). Dropped m*l, l*l ~ 2^-24 -> fp32-class.
// BK=32 (two k16 steps per smem fill -> half the syncthreads of R10).
// Smem row stride 20 u32: fragment addr 20g+q mod 32 all-distinct (validated).
struct GSeg {
    const uint32_t* A;  // plane 0 base; row stride 64 pairs
    int aplane;         // plane stride (rows*64)
    const uint32_t* W;  // plane 0 base (may be column slice)
    int wpairs;         // row stride in pairs
    int wplane;         // plane stride
};

#define MMA_BF16(accp, a0, a1, a2, a3, bb0, bb1)                              \
    asm volatile(                                                             \
        "mma.sync.aligned.m16n8k16.row.col.f32.bf16.bf16.f32 "                \
        "{%0,%1,%2,%3}, {%4,%5,%6,%7}, {%8,%9}, {%0,%1,%2,%3};\n"             \
        : "+f"((accp)[0]), "+f"((accp)[1]), "+f"((accp)[2]), "+f"((accp)[3])  \
        : "r"(a0), "r"(a1), "r"(a2), "r"(a3), "r"(bb0), "r"(bb1))

#define MMA_BF16_Z(outp, a0, a1, a2, a3, bb0, bb1)                            \
    asm volatile(                                                             \
        "mma.sync.aligned.m16n8k16.row.col.f32.bf16.bf16.f32 "                \
        "{%0,%1,%2,%3}, {%4,%5,%6,%7}, {%8,%9}, {%10,%10,%10,%10};\n"         \
        : "=f"((outp)[0]), "=f"((outp)[1]), "=f"((outp)[2]), "=f"((outp)[3])  \
        : "r"(a0), "r"(a1), "r"(a2), "r"(a3), "r"(bb0), "r"(bb1), "f"(0.0f))

#define SSTU 20  // u32 row stride (16 data pairs + 4 pad)

__global__ void __launch_bounds__(256) k_gemm_planes(
    GSeg s0, GSeg s1, GSeg s2,
    const float* __restrict__ b1, const float* __restrict__ b2,
    float* __restrict__ Y, int N) {
    __shared__ uint32_t As[3][64][SSTU];
    __shared__ uint32_t Bs[3][64][SSTU];

    int m0 = blockIdx.y * 64, n0 = blockIdx.x * 64;
    int t = threadIdx.x;
    int lane = t & 31;
    int warp = t >> 5;
    int wm = (warp >> 2) * 32;
    int wn = (warp & 3) * 16;
    int g = lane >> 2;
    int q = lane & 3;

    int row = t >> 2;        // 0..63
    int qq = t & 3;          // pair-group 0..3 (loads pairs 4qq..4qq+3)

    float accHi[2][2][4], comp[2][2][4], accLo[2][2][4];
    #pragma unroll
    for (int a = 0; a < 2; a++)
        #pragma unroll
        for (int b = 0; b < 2; b++)
            #pragma unroll
            for (int cix = 0; cix < 4; cix++) {
                accHi[a][b][cix] = 0.0f;
                comp[a][b][cix] = 0.0f;
                accLo[a][b][cix] = 0.0f;
            }

    GSeg segs[3] = {s0, s1, s2};

    #pragma unroll 1
    for (int s = 0; s < 3; s++) {
        GSeg sg = segs[s];
        if (!sg.A) break;
        #pragma unroll 1
        for (int kt = 0; kt < 4; kt++) {   // K=128 -> 4 tiles of 32 (16 pairs)
            int k0p = kt * 16;
            uint4 aLd[3], wLd[3];
            #pragma unroll
            for (int pl = 0; pl < 3; pl++) {
                aLd[pl] = *(const uint4*)(sg.A + (size_t)pl * sg.aplane +
                                          (size_t)(m0 + row) * 64 + k0p + 4 * qq);
                wLd[pl] = *(const uint4*)(sg.W + (size_t)pl * sg.wplane +
                                          (size_t)(n0 + row) * sg.wpairs + k0p + 4 * qq);
            }
            __syncthreads();
            #pragma unroll
            for (int pl = 0; pl < 3; pl++) {
                *(uint4*)&As[pl][row][4 * qq] = aLd[pl];
                *(uint4*)&Bs[pl][row][4 * qq] = wLd[pl];
            }
            __syncthreads();
            #pragma unroll
            for (int kkp = 0; kkp < 16; kkp += 8) {
                uint32_t af[3][2][4], bf[3][2][2];
                #pragma unroll
                for (int pl = 0; pl < 3; pl++) {
                    #pragma unroll
                    for (int mt = 0; mt < 2; mt++) {
                        int m_ = wm + mt * 16;
                        af[pl][mt][0] = As[pl][m_ + g][kkp + q];
                        af[pl][mt][1] = As[pl][m_ + g + 8][kkp + q];
                        af[pl][mt][2] = As[pl][m_ + g][kkp + q + 4];
                        af[pl][mt][3] = As[pl][m_ + g + 8][kkp + q + 4];
                    }
                    #pragma unroll
                    for (int nt = 0; nt < 2; nt++) {
                        int n_ = wn + nt * 8;
                        bf[pl][nt][0] = Bs[pl][n_ + g][kkp + q];
                        bf[pl][nt][1] = Bs[pl][n_ + g][kkp + q + 4];
                    }
                }
                #pragma unroll
                for (int mt = 0; mt < 2; mt++)
                    #pragma unroll
                    for (int nt = 0; nt < 2; nt++) {
                        MMA_BF16(accLo[mt][nt], af[2][mt][0], af[2][mt][1], af[2][mt][2],
                                 af[2][mt][3], bf[0][nt][0], bf[0][nt][1]);  // l*h
                        MMA_BF16(accLo[mt][nt], af[1][mt][0], af[1][mt][1], af[1][mt][2],
                                 af[1][mt][3], bf[1][nt][0], bf[1][nt][1]);  // m*m
                        MMA_BF16(accLo[mt][nt], af[0][mt][0], af[0][mt][1], af[0][mt][2],
                                 af[0][mt][3], bf[2][nt][0], bf[2][nt][1]);  // h*l
                        MMA_BF16(accLo[mt][nt], af[1][mt][0], af[1][mt][1], af[1][mt][2],
                                 af[1][mt][3], bf[0][nt][0], bf[0][nt][1]);  // m*h
                        MMA_BF16(accLo[mt][nt], af[0][mt][0], af[0][mt][1], af[0][mt][2],
                                 af[0][mt][3], bf[1][nt][0], bf[1][nt][1]);  // h*m
                        float tmp[4];
                        MMA_BF16_Z(tmp, af[0][mt][0], af[0][mt][1], af[0][mt][2],
                                   af[0][mt][3], bf[0][nt][0], bf[0][nt][1]);
                        #pragma unroll
                        for (int i = 0; i < 4; i++) {
                            float y = tmp[i] - comp[mt][nt][i];
                            float tsum = accHi[mt][nt][i] + y;
                            comp[mt][nt][i] = (tsum - accHi[mt][nt][i]) - y;
                            accHi[mt][nt][i] = tsum;
                        }
                    }
            }
        }
    }

    #pragma unroll
    for (int mt = 0; mt < 2; mt++)
        #pragma unroll
        for (int nt = 0; nt < 2; nt++) {
            int r0 = m0 + wm + mt * 16 + g;
            int r1 = r0 + 8;
            int c = n0 + wn + nt * 8 + 2 * q;
            float bs0 = (b1 ? b1[c] : 0.f) + (b2 ? b2[c] : 0.f);
            float bs1 = (b1 ? b1[c + 1] : 0.f) + (b2 ? b2[c + 1] : 0.f);
            float o0 = accHi[mt][nt][0] + (accLo[mt][nt][0] - comp[mt][nt][0]);
            float o1 = accHi[mt][nt][1] + (accLo[mt][nt][1] - comp[mt][nt][1]);
            float o2 = accHi[mt][nt][2] + (accLo[mt][nt][2] - comp[mt][nt][2]);
            float o3 = accHi[mt][nt][3] + (accLo[mt][nt][3] - comp[mt][nt][3]);
            Y[(size_t)r0 * N + c]     = o0 + bs0;
            Y[(size_t)r0 * N + c + 1] = o1 + bs1;
            Y[(size_t)r1 * N + c]     = o2 + bs0;
            Y[(size_t)r1 * N + c + 1] = o3 + bs1;
        }
}

// ---------------- host driver ------------------------------------------------
extern "C" void kernel_launch(void* const* d_in, const int* in_sizes, int n_in,
                              void* d_out, int out_size) {
    const float* L_state  = (const float*)d_in[0];
    const float* hidden_L = (const float*)d_in[2];
    const float* hidden_C = (const float*)d_in[3];
    const float* Mmat     = (const float*)d_in[4];
    int o = (n_in >= 18) ? 6 : 5;  // skip scalar n_vars if present
    const float* W_lc  = (const float*)d_in[o + 0];
    const float* b_lc  = (const float*)d_in[o + 1];
    const float* W_cl  = (const float*)d_in[o + 2];
    const float* b_cl  = (const float*)d_in[o + 3];
    const float* Wih_C = (const float*)d_in[o + 4];
    const float* Whh_C = (const float*)d_in[o + 5];
    const float* bih_C = (const float*)d_in[o + 6];
    const float* bhh_C = (const float*)d_in[o + 7];
    const float* Wih_L = (const float*)d_in[o + 8];
    const float* Whh_L = (const float*)d_in[o + 9];
    const float* bih_L = (const float*)d_in[o + 10];
    const float* bhh_L = (const float*)d_in[o + 11];

    void* p;
    cudaGetSymbolAddress(&p, g_hL);     float* hL     = (float*)p;
    cudaGetSymbolAddress(&p, g_hC);     float* hC     = (float*)p;
    cudaGetSymbolAddress(&p, g_LCpre);  float* LCpre  = (float*)p;
    cudaGetSymbolAddress(&p, g_CLpre);  float* CLpre  = (float*)p;
    cudaGetSymbolAddress(&p, g_gatesC); float* gatesC = (float*)p;
    cudaGetSymbolAddress(&p, g_gatesL); float* gatesL = (float*)p;
    cudaGetSymbolAddress(&p, g_ptrL);   int* ptrL = (int*)p;
    cudaGetSymbolAddress(&p, g_ptrC);   int* ptrC = (int*)p;
    cudaGetSymbolAddress(&p, g_colL);   int* colL = (int*)p;
    cudaGetSymbolAddress(&p, g_colC);   int* colC = (int*)p;
    cudaGetSymbolAddress(&p, g_cntL);   int* cntL = (int*)p;
    cudaGetSymbolAddress(&p, g_cntC);   int* cntC = (int*)p;

    uint32_t *pW_lc, *pW_cl, *pWih_C, *pWhh_C, *pWih_L, *pWhh_L;
    uint32_t *pL0, *pL1, *phL, *pCmsg, *phC, *pCs, *pLmsg;
    cudaGetSymbolAddress(&p, g_pW_lc);  pW_lc  = (uint32_t*)p;
    cudaGetSymbolAddress(&p, g_pW_cl);  pW_cl  = (uint32_t*)p;
    cudaGetSymbolAddress(&p, g_pWih_C); pWih_C = (uint32_t*)p;
    cudaGetSymbolAddress(&p, g_pWhh_C); pWhh_C = (uint32_t*)p;
    cudaGetSymbolAddress(&p, g_pWih_L); pWih_L = (uint32_t*)p;
    cudaGetSymbolAddress(&p, g_pWhh_L); pWhh_L = (uint32_t*)p;
    cudaGetSymbolAddress(&p, g_pL);     pL0 = (uint32_t*)p; pL1 = pL0 + 3 * NLIT * 64;
    cudaGetSymbolAddress(&p, g_phL);    phL   = (uint32_t*)p;
    cudaGetSymbolAddress(&p, g_pCmsg);  pCmsg = (uint32_t*)p;
    cudaGetSymbolAddress(&p, g_phC);    phC   = (uint32_t*)p;
    cudaGetSymbolAddress(&p, g_pCs);    pCs   = (uint32_t*)p;
    cudaGetSymbolAddress(&p, g_pLmsg);  pLmsg = (uint32_t*)p;

    const int PSL = NLIT * 64;   // plane stride, literal-sized
    const int PSC = NCLA * 64;   // plane stride, clause-sized

    // ---- CSR build (redone every launch; no caching allowed) ----
    k_reset<<<(NCLA + 255) / 256, 256>>>();
    k_count<<<2048, 256>>>(Mmat);
    k_scan<<<1, 1024>>>(cntL, ptrL, NLIT);
    k_scan<<<1, 1024>>>(cntC, ptrC, NCLA);
    k_fill<<<512, 256>>>();

    // ---- split weights once per launch ----
    k_split<<<(128 * 64 + 255) / 256, 256>>>(W_lc, pW_lc, 128 * 64, 128 * 64);
    k_split<<<(128 * 64 + 255) / 256, 256>>>(W_cl, pW_cl, 128 * 64, 128 * 64);
    k_split<<<(512 * 64 + 255) / 256, 256>>>(Wih_C, pWih_C, 512 * 64, 512 * 64);
    k_split<<<(512 * 64 + 255) / 256, 256>>>(Whh_C, pWhh_C, 512 * 64, 512 * 64);
    k_split<<<(512 * 128 + 255) / 256, 256>>>(Wih_L, pWih_L, 512 * 128, 512 * 128);
    k_split<<<(512 * 64 + 255) / 256, 256>>>(Whh_L, pWhh_L, 512 * 64, 512 * 64);

    // ---- state init ----
    cudaMemcpyAsync(hC, hidden_C, sizeof(float) * NCLA * D, cudaMemcpyDeviceToDevice);
    cudaMemcpyAsync(hL, hidden_L, sizeof(float) * NLIT * D, cudaMemcpyDeviceToDevice);
    cudaMemsetAsync(phC, 0, sizeof(uint32_t) * 3 * PSC);   // split(0) == 0
    cudaMemsetAsync(phL, 0, sizeof(uint32_t) * 3 * PSL);
    k_split<<<(NLIT * 64 + 255) / 256, 256>>>(L_state, pL0, NLIT * 64, PSL);

    GSeg z = {nullptr, 0, nullptr, 0, 0};

    // ---- T message-passing rounds ----
    for (int r = 0; r < TSTEPS; r++) {
        uint32_t* pLcur  = (r & 1) ? pL1 : pL0;
        uint32_t* pLnext = (r & 1) ? pL0 : pL1;
        float* hOutFinal = (r == TSTEPS - 1) ? (float*)d_out : nullptr;

        // LC_pre = L @ W_lc^T + b_lc
        GSeg a1 = {pLcur, PSL, pW_lc, 64, 128 * 64};
        k_gemm_planes<<<dim3(D / 64, NLIT / 64), 256>>>(a1, z, z, b_lc, nullptr, LCpre, D);
        // LC_msgs = M^T @ LC_pre  (emits planes)
        k_spmm_split<<<NCLA / 4, 128>>>(ptrC, colC, LCpre, pCmsg, PSC);
        // C gates = Cmsg @ Wih_C^T + hC @ Whh_C^T + biases
        GSeg c1 = {pCmsg, PSC, pWih_C, 64, 512 * 64};
        GSeg c2 = {phC, PSC, pWhh_C, 64, 512 * 64};
        k_gemm_planes<<<dim3(4 * D / 64, NCLA / 64), 256>>>(c1, c2, z, bih_C, bhh_C,
                                                            gatesC, 4 * D);
        // C LSTM: h -> pCs planes, c -> hC fp32 + phC planes
        k_lstm_split<<<(NCLA * 64 + 255) / 256, 256>>>(gatesC, hC, nullptr,
                                                       pCs, PSC, phC, PSC, NCLA);
        // CL_pre = Cs @ W_cl^T + b_cl
        GSeg d1 = {pCs, PSC, pW_cl, 64, 128 * 64};
        k_gemm_planes<<<dim3(D / 64, NCLA / 64), 256>>>(d1, z, z, b_cl, nullptr, CLpre, D);
        // CL_msgs = M @ CL_pre  (emits planes)
        k_spmm_split<<<NLIT / 4, 128>>>(ptrL, colL, CLpre, pLmsg, PSL);
        // L gates = [Lmsg | Lcur] @ Wih_L^T + hL @ Whh_L^T + biases (concat fused)
        GSeg e1 = {pLmsg, PSL, pWih_L, 128, 512 * 128};
        GSeg e2 = {pLcur, PSL, pWih_L + 64, 128, 512 * 128};
        GSeg e3 = {phL, PSL, pWhh_L, 64, 512 * 64};
        k_gemm_planes<<<dim3(4 * D / 64, NLIT / 64), 256>>>(e1, e2, e3, bih_L, bhh_L,
                                                            gatesL, 4 * D);
        // L LSTM: h -> pLnext planes (+ d_out fp32 on last round), c -> hL + phL
        k_lstm_split<<<(NLIT * 64 + 255) / 256, 256>>>(gatesL, hL, hOutFinal,
                                                       pLnext, PSL, phL, PSL, NLIT);
    }
}

// round 13
// speedup vs baseline: 1.7399x; 1.2380x over previous
#include <cuda_runtime.h>
#include <cuda_fp16.h>
#include <math.h>
#include <stdint.h>

#define D 128
#define NLIT 8000
#define NCLA 16000
#define TSTEPS 8
#define MAX_NNZ (1 << 20)

// ---------------- persistent scratch (device globals; no allocs) -------------
__device__ float g_LCpre[NLIT * D];
__device__ float g_hC[NCLA * D];
__device__ float g_CLpre[NCLA * D];
__device__ float g_hL[NLIT * D];
__device__ float g_gatesC[NCLA * 4 * D];
__device__ float g_gatesL[NLIT * 4 * D];

// fp16 plane buffers: layout [2][rows][K/2] u32 (plane stride = rows*K/2)
__device__ uint32_t g_pW_lc[2 * 128 * 64];
__device__ uint32_t g_pW_cl[2 * 128 * 64];
__device__ uint32_t g_pWih_C[2 * 512 * 64];
__device__ uint32_t g_pWhh_C[2 * 512 * 64];
__device__ uint32_t g_pWih_L[2 * 512 * 128];
__device__ uint32_t g_pWhh_L[2 * 512 * 64];
__device__ uint32_t g_pL[2][2 * NLIT * 64];
__device__ uint32_t g_phL[2 * NLIT * 64];
__device__ uint32_t g_pCmsg[2 * NCLA * 64];
__device__ uint32_t g_phC[2 * NCLA * 64];
__device__ uint32_t g_pCs[2 * NCLA * 64];
__device__ uint32_t g_pLmsg[2 * NLIT * 64];

__device__ int g_nnz;
__device__ int g_pairs[MAX_NNZ];
__device__ int g_cntL[NLIT], g_cntC[NCLA];
__device__ int g_fillL[NLIT], g_fillC[NCLA];
__device__ int g_ptrL[NLIT + 1], g_ptrC[NCLA + 1];
__device__ int g_colL[MAX_NNZ];
__device__ int g_colC[MAX_NNZ];

// split two fp32 into 2 packed f16x2 planes: x = h + m + eps, |eps| <= max(|x|*2^-23, 2^-24)
__device__ __forceinline__ void f16_split2(float x0, float x1,
                                           uint32_t& hp, uint32_t& mp) {
    __half h0 = __float2half_rn(x0), h1 = __float2half_rn(x1);
    float r0 = x0 - __half2float(h0);
    float r1 = x1 - __half2float(h1);
    __half m0 = __float2half_rn(r0), m1 = __float2half_rn(r1);
    hp = (uint32_t)__half_as_ushort(h0) | ((uint32_t)__half_as_ushort(h1) << 16);
    mp = (uint32_t)__half_as_ushort(m0) | ((uint32_t)__half_as_ushort(m1) << 16);
}

// ---------------- CSR build ---------------------------------------------------
__global__ void k_reset() {
    int i = blockIdx.x * blockDim.x + threadIdx.x;
    if (i < NLIT) { g_cntL[i] = 0; g_fillL[i] = 0; }
    if (i < NCLA) { g_cntC[i] = 0; g_fillC[i] = 0; }
    if (i == 0) g_nnz = 0;
}

__global__ void k_count(const float* __restrict__ M) {
    const int total4 = (NLIT * NCLA) / 4;  // exact trip count -> warp-uniform ballot
    int stride = gridDim.x * blockDim.x;
    int lane = threadIdx.x & 31;
    for (int i = blockIdx.x * blockDim.x + threadIdx.x; i < total4; i += stride) {
        float4 v = ((const float4*)M)[i];
        int base = i << 2;
        float vals[4] = {v.x, v.y, v.z, v.w};
        #pragma unroll
        for (int jj = 0; jj < 4; jj++) {
            bool nz = (vals[jj] != 0.0f);
            unsigned m = __ballot_sync(0xffffffffu, nz);
            if (!m) continue;
            int ldr = __ffs(m) - 1;
            int basep = 0;
            if (lane == ldr) basep = atomicAdd(&g_nnz, __popc(m));
            basep = __shfl_sync(0xffffffffu, basep, ldr);
            if (nz) {
                int idx = base + jj;
                int l = idx / NCLA;
                int c = idx - l * NCLA;
                int p = basep + __popc(m & ((1u << lane) - 1u));
                if (p < MAX_NNZ) g_pairs[p] = idx;
                atomicAdd(&g_cntL[l], 1);
                atomicAdd(&g_cntC[c], 1);
            }
        }
    }
}

// block 0 scans cntL -> ptrL (NLIT), block 1 scans cntC -> ptrC (NCLA)
__global__ void k_scan2() {
    __shared__ int sums[1024];
    const int* cnt = blockIdx.x ? g_cntC : g_cntL;
    int* ptr = blockIdx.x ? g_ptrC : g_ptrL;
    int n = blockIdx.x ? NCLA : NLIT;
    int t = threadIdx.x;
    int chunk = (n + blockDim.x - 1) / blockDim.x;
    int start = t * chunk;
    int end = min(start + chunk, n);
    int s = 0;
    for (int i = start; i < end; i++) { ptr[i] = s; s += cnt[i]; }
    sums[t] = s;
    __syncthreads();
    for (int off = 1; off < 1024; off <<= 1) {
        int v = (t >= off) ? sums[t - off] : 0;
        __syncthreads();
        sums[t] += v;
        __syncthreads();
    }
    int base = (t == 0) ? 0 : sums[t - 1];
    for (int i = start; i < end; i++) ptr[i] += base;
    if (t == blockDim.x - 1) ptr[n] = sums[t];
}

__global__ void k_fill() {
    int nnz = g_nnz;
    if (nnz > MAX_NNZ) nnz = MAX_NNZ;
    int stride = gridDim.x * blockDim.x;
    for (int p = blockIdx.x * blockDim.x + threadIdx.x; p < nnz; p += stride) {
        int idx = g_pairs[p];
        int l = idx / NCLA;
        int c = idx - l * NCLA;
        int a = atomicAdd(&g_fillL[l], 1);
        g_colL[g_ptrL[l] + a] = c;
        int b = atomicAdd(&g_fillC[c], 1);
        g_colC[g_ptrC[c] + b] = l;
    }
}

// ---------------- generic fp32 -> 2-plane split (weights, round-0 L) ---------
__global__ void k_split(const float* __restrict__ X, uint32_t* __restrict__ planes,
                        int npairs, int planeStride) {
    int i = blockIdx.x * blockDim.x + threadIdx.x;
    if (i >= npairs) return;
    uint32_t h, m;
    f16_split2(X[2 * i], X[2 * i + 1], h, m);
    planes[i] = h;
    planes[planeStride + i] = m;
}

// ---------------- SpMM: warp per row, emits fp16 planes directly -------------
__global__ void __launch_bounds__(128) k_spmm_split(
    const int* __restrict__ ptr, const int* __restrict__ col,
    const float* __restrict__ X, uint32_t* __restrict__ planes, int planeStride) {
    int r = blockIdx.x * 4 + (threadIdx.x >> 5);
    int lane = threadIdx.x & 31;
    int beg = ptr[r], end = ptr[r + 1];
    float4 acc = make_float4(0.f, 0.f, 0.f, 0.f);
    int j = beg;
    for (; j + 1 < end; j += 2) {
        float4 v0 = *((const float4*)(X + (size_t)col[j] * D) + lane);
        float4 v1 = *((const float4*)(X + (size_t)col[j + 1] * D) + lane);
        acc.x += v0.x + v1.x; acc.y += v0.y + v1.y;
        acc.z += v0.z + v1.z; acc.w += v0.w + v1.w;
    }
    if (j < end) {
        float4 v = *((const float4*)(X + (size_t)col[j] * D) + lane);
        acc.x += v.x; acc.y += v.y; acc.z += v.z; acc.w += v.w;
    }
    uint32_t h0, m0, h1, m1;
    f16_split2(acc.x, acc.y, h0, m0);
    f16_split2(acc.z, acc.w, h1, m1);
    int o = r * 64 + lane * 2;
    planes[o] = h0;                   planes[o + 1] = h1;
    planes[planeStride + o] = m0;     planes[planeStride + o + 1] = m1;
}

// ---------------- LSTM pointwise, emits fp32 state + fp16 planes -------------
__device__ __forceinline__ float sigm(float x) { return 1.0f / (1.0f + expf(-x)); }

// gate order (torch): i, f, g, o. c and h come from the same buffer (reference
// carries c_new as both h and c of the next round). Each thread does 2 elems.
__global__ void k_lstm_split(const float* __restrict__ gates,
                             float* __restrict__ c_state,          // in/out fp32
                             float* __restrict__ h_fp32,           // optional
                             uint32_t* __restrict__ h_planes, int hPS,
                             uint32_t* __restrict__ c_planes, int cPS,
                             int rows) {
    int i = blockIdx.x * blockDim.x + threadIdx.x;  // pair index
    if (i >= rows * 64) return;
    int r = i >> 6, pr = i & 63;
    int d0 = pr * 2;
    const float* gp = gates + (size_t)r * 4 * D;
    float c0 = c_state[r * D + d0], c1 = c_state[r * D + d0 + 1];
    float cn0 = sigm(gp[D + d0]) * c0 + sigm(gp[d0]) * tanhf(gp[2 * D + d0]);
    float cn1 = sigm(gp[D + d0 + 1]) * c1 + sigm(gp[d0 + 1]) * tanhf(gp[2 * D + d0 + 1]);
    float hn0 = sigm(gp[3 * D + d0]) * tanhf(cn0);
    float hn1 = sigm(gp[3 * D + d0 + 1]) * tanhf(cn1);
    c_state[r * D + d0] = cn0;
    c_state[r * D + d0 + 1] = cn1;
    if (h_fp32) { h_fp32[r * D + d0] = hn0; h_fp32[r * D + d0 + 1] = hn1; }
    uint32_t h, m;
    f16_split2(hn0, hn1, h, m);
    h_planes[i] = h; h_planes[hPS + i] = m;
    f16_split2(cn0, cn1, h, m);
    c_planes[i] = h; c_planes[cPS + i] = m;
}

// ---------------- fp16x2 tensor-core GEMM on pre-split planes ----------------
// Numeric discipline validated R9/R10: dominant h*h per k16 step via C=0
// fragments + register Kahan (unbiased RN); low-order products C-chained into
// accLo where the truncation bias is scaled by their magnitude (<= 2^-11).
// fp16 2-way split keeps ALL cross products (h*h, h*m, m*h, m*m) -> nothing
// above 2^-23 dropped -> fp32-class. 4 mmas per k16 vs bf16x3's 6 (-33%).
// Smem row stride 20 u32: fragment addr 20g+q mod 32 all-distinct (validated).
struct GSeg {
    const uint32_t* A;  // plane 0 base; row stride 64 pairs
    int aplane;         // plane stride (rows*64)
    const uint32_t* W;  // plane 0 base (may be column slice)
    int wpairs;         // row stride in pairs
    int wplane;         // plane stride
};

#define MMA_F16(accp, a0, a1, a2, a3, bb0, bb1)                               \
    asm volatile(                                                             \
        "mma.sync.aligned.m16n8k16.row.col.f32.f16.f16.f32 "                  \
        "{%0,%1,%2,%3}, {%4,%5,%6,%7}, {%8,%9}, {%0,%1,%2,%3};\n"             \
        : "+f"((accp)[0]), "+f"((accp)[1]), "+f"((accp)[2]), "+f"((accp)[3])  \
        : "r"(a0), "r"(a1), "r"(a2), "r"(a3), "r"(bb0), "r"(bb1))

#define MMA_F16_Z(outp, a0, a1, a2, a3, bb0, bb1)                             \
    asm volatile(                                                             \
        "mma.sync.aligned.m16n8k16.row.col.f32.f16.f16.f32 "                  \
        "{%0,%1,%2,%3}, {%4,%5,%6,%7}, {%8,%9}, {%10,%10,%10,%10};\n"         \
        : "=f"((outp)[0]), "=f"((outp)[1]), "=f"((outp)[2]), "=f"((outp)[3])  \
        : "r"(a0), "r"(a1), "r"(a2), "r"(a3), "r"(bb0), "r"(bb1), "f"(0.0f))

#define SSTU 20  // u32 row stride (16 data pairs + 4 pad)

__global__ void __launch_bounds__(256) k_gemm_planes(
    GSeg s0, GSeg s1, GSeg s2,
    const float* __restrict__ b1, const float* __restrict__ b2,
    float* __restrict__ Y, int N) {
    __shared__ uint32_t As[2][64][SSTU];
    __shared__ uint32_t Bs[2][64][SSTU];

    int m0 = blockIdx.y * 64, n0 = blockIdx.x * 64;
    int t = threadIdx.x;
    int lane = t & 31;
    int warp = t >> 5;
    int wm = (warp >> 2) * 32;
    int wn = (warp & 3) * 16;
    int g = lane >> 2;
    int q = lane & 3;

    int row = t >> 2;        // 0..63
    int qq = t & 3;          // pair-group 0..3 (loads pairs 4qq..4qq+3)

    float accHi[2][2][4], comp[2][2][4], accLo[2][2][4];
    #pragma unroll
    for (int a = 0; a < 2; a++)
        #pragma unroll
        for (int b = 0; b < 2; b++)
            #pragma unroll
            for (int cix = 0; cix < 4; cix++) {
                accHi[a][b][cix] = 0.0f;
                comp[a][b][cix] = 0.0f;
                accLo[a][b][cix] = 0.0f;
            }

    GSeg segs[3] = {s0, s1, s2};

    #pragma unroll 1
    for (int s = 0; s < 3; s++) {
        GSeg sg = segs[s];
        if (!sg.A) break;
        #pragma unroll 1
        for (int kt = 0; kt < 4; kt++) {   // K=128 -> 4 tiles of 32 (16 pairs)
            int k0p = kt * 16;
            uint4 aLd[2], wLd[2];
            #pragma unroll
            for (int pl = 0; pl < 2; pl++) {
                aLd[pl] = *(const uint4*)(sg.A + (size_t)pl * sg.aplane +
                                          (size_t)(m0 + row) * 64 + k0p + 4 * qq);
                wLd[pl] = *(const uint4*)(sg.W + (size_t)pl * sg.wplane +
                                          (size_t)(n0 + row) * sg.wpairs + k0p + 4 * qq);
            }
            __syncthreads();
            #pragma unroll
            for (int pl = 0; pl < 2; pl++) {
                *(uint4*)&As[pl][row][4 * qq] = aLd[pl];
                *(uint4*)&Bs[pl][row][4 * qq] = wLd[pl];
            }
            __syncthreads();
            #pragma unroll
            for (int kkp = 0; kkp < 16; kkp += 8) {
                uint32_t af[2][2][4], bf[2][2][2];
                #pragma unroll
                for (int pl = 0; pl < 2; pl++) {
                    #pragma unroll
                    for (int mt = 0; mt < 2; mt++) {
                        int m_ = wm + mt * 16;
                        af[pl][mt][0] = As[pl][m_ + g][kkp + q];
                        af[pl][mt][1] = As[pl][m_ + g + 8][kkp + q];
                        af[pl][mt][2] = As[pl][m_ + g][kkp + q + 4];
                        af[pl][mt][3] = As[pl][m_ + g + 8][kkp + q + 4];
                    }
                    #pragma unroll
                    for (int nt = 0; nt < 2; nt++) {
                        int n_ = wn + nt * 8;
                        bf[pl][nt][0] = Bs[pl][n_ + g][kkp + q];
                        bf[pl][nt][1] = Bs[pl][n_ + g][kkp + q + 4];
                    }
                }
                #pragma unroll
                for (int mt = 0; mt < 2; mt++)
                    #pragma unroll
                    for (int nt = 0; nt < 2; nt++) {
                        // low-order products, smallest first (C-chained)
                        MMA_F16(accLo[mt][nt], af[1][mt][0], af[1][mt][1], af[1][mt][2],
                                af[1][mt][3], bf[1][nt][0], bf[1][nt][1]);  // m*m
                        MMA_F16(accLo[mt][nt], af[1][mt][0], af[1][mt][1], af[1][mt][2],
                                af[1][mt][3], bf[0][nt][0], bf[0][nt][1]);  // m*h
                        MMA_F16(accLo[mt][nt], af[0][mt][0], af[0][mt][1], af[0][mt][2],
                                af[0][mt][3], bf[1][nt][0], bf[1][nt][1]);  // h*m
                        // dominant h*h: fresh C=0 fragment, Kahan into registers
                        float tmp[4];
                        MMA_F16_Z(tmp, af[0][mt][0], af[0][mt][1], af[0][mt][2],
                                  af[0][mt][3], bf[0][nt][0], bf[0][nt][1]);
                        #pragma unroll
                        for (int i = 0; i < 4; i++) {
                            float y = tmp[i] - comp[mt][nt][i];
                            float tsum = accHi[mt][nt][i] + y;
                            comp[mt][nt][i] = (tsum - accHi[mt][nt][i]) - y;
                            accHi[mt][nt][i] = tsum;
                        }
                    }
            }
        }
    }

    #pragma unroll
    for (int mt = 0; mt < 2; mt++)
        #pragma unroll
        for (int nt = 0; nt < 2; nt++) {
            int r0 = m0 + wm + mt * 16 + g;
            int r1 = r0 + 8;
            int c = n0 + wn + nt * 8 + 2 * q;
            float bs0 = (b1 ? b1[c] : 0.f) + (b2 ? b2[c] : 0.f);
            float bs1 = (b1 ? b1[c + 1] : 0.f) + (b2 ? b2[c + 1] : 0.f);
            float o0 = accHi[mt][nt][0] + (accLo[mt][nt][0] - comp[mt][nt][0]);
            float o1 = accHi[mt][nt][1] + (accLo[mt][nt][1] - comp[mt][nt][1]);
            float o2 = accHi[mt][nt][2] + (accLo[mt][nt][2] - comp[mt][nt][2]);
            float o3 = accHi[mt][nt][3] + (accLo[mt][nt][3] - comp[mt][nt][3]);
            Y[(size_t)r0 * N + c]     = o0 + bs0;
            Y[(size_t)r0 * N + c + 1] = o1 + bs1;
            Y[(size_t)r1 * N + c]     = o2 + bs0;
            Y[(size_t)r1 * N + c + 1] = o3 + bs1;
        }
}

// ---------------- host driver ------------------------------------------------
extern "C" void kernel_launch(void* const* d_in, const int* in_sizes, int n_in,
                              void* d_out, int out_size) {
    const float* L_state  = (const float*)d_in[0];
    const float* hidden_L = (const float*)d_in[2];
    const float* hidden_C = (const float*)d_in[3];
    const float* Mmat     = (const float*)d_in[4];
    int o = (n_in >= 18) ? 6 : 5;  // skip scalar n_vars if present
    const float* W_lc  = (const float*)d_in[o + 0];
    const float* b_lc  = (const float*)d_in[o + 1];
    const float* W_cl  = (const float*)d_in[o + 2];
    const float* b_cl  = (const float*)d_in[o + 3];
    const float* Wih_C = (const float*)d_in[o + 4];
    const float* Whh_C = (const float*)d_in[o + 5];
    const float* bih_C = (const float*)d_in[o + 6];
    const float* bhh_C = (const float*)d_in[o + 7];
    const float* Wih_L = (const float*)d_in[o + 8];
    const float* Whh_L = (const float*)d_in[o + 9];
    const float* bih_L = (const float*)d_in[o + 10];
    const float* bhh_L = (const float*)d_in[o + 11];

    void* p;
    cudaGetSymbolAddress(&p, g_hL);     float* hL     = (float*)p;
    cudaGetSymbolAddress(&p, g_hC);     float* hC     = (float*)p;
    cudaGetSymbolAddress(&p, g_LCpre);  float* LCpre  = (float*)p;
    cudaGetSymbolAddress(&p, g_CLpre);  float* CLpre  = (float*)p;
    cudaGetSymbolAddress(&p, g_gatesC); float* gatesC = (float*)p;
    cudaGetSymbolAddress(&p, g_gatesL); float* gatesL = (float*)p;
    cudaGetSymbolAddress(&p, g_ptrL);   int* ptrL = (int*)p;
    cudaGetSymbolAddress(&p, g_ptrC);   int* ptrC = (int*)p;
    cudaGetSymbolAddress(&p, g_colL);   int* colL = (int*)p;
    cudaGetSymbolAddress(&p, g_colC);   int* colC = (int*)p;

    uint32_t *pW_lc, *pW_cl, *pWih_C, *pWhh_C, *pWih_L, *pWhh_L;
    uint32_t *pL0, *pL1, *phL, *pCmsg, *phC, *pCs, *pLmsg;
    cudaGetSymbolAddress(&p, g_pW_lc);  pW_lc  = (uint32_t*)p;
    cudaGetSymbolAddress(&p, g_pW_cl);  pW_cl  = (uint32_t*)p;
    cudaGetSymbolAddress(&p, g_pWih_C); pWih_C = (uint32_t*)p;
    cudaGetSymbolAddress(&p, g_pWhh_C); pWhh_C = (uint32_t*)p;
    cudaGetSymbolAddress(&p, g_pWih_L); pWih_L = (uint32_t*)p;
    cudaGetSymbolAddress(&p, g_pWhh_L); pWhh_L = (uint32_t*)p;
    cudaGetSymbolAddress(&p, g_pL);     pL0 = (uint32_t*)p; pL1 = pL0 + 2 * NLIT * 64;
    cudaGetSymbolAddress(&p, g_phL);    phL   = (uint32_t*)p;
    cudaGetSymbolAddress(&p, g_pCmsg);  pCmsg = (uint32_t*)p;
    cudaGetSymbolAddress(&p, g_phC);    phC   = (uint32_t*)p;
    cudaGetSymbolAddress(&p, g_pCs);    pCs   = (uint32_t*)p;
    cudaGetSymbolAddress(&p, g_pLmsg);  pLmsg = (uint32_t*)p;

    const int PSL = NLIT * 64;   // plane stride, literal-sized
    const int PSC = NCLA * 64;   // plane stride, clause-sized

    // ---- CSR build (redone every launch; no caching allowed) ----
    k_reset<<<(NCLA + 255) / 256, 256>>>();
    k_count<<<2048, 256>>>(Mmat);
    k_scan2<<<2, 1024>>>();
    k_fill<<<512, 256>>>();

    // ---- split weights once per launch ----
    k_split<<<(128 * 64 + 255) / 256, 256>>>(W_lc, pW_lc, 128 * 64, 128 * 64);
    k_split<<<(128 * 64 + 255) / 256, 256>>>(W_cl, pW_cl, 128 * 64, 128 * 64);
    k_split<<<(512 * 64 + 255) / 256, 256>>>(Wih_C, pWih_C, 512 * 64, 512 * 64);
    k_split<<<(512 * 64 + 255) / 256, 256>>>(Whh_C, pWhh_C, 512 * 64, 512 * 64);
    k_split<<<(512 * 128 + 255) / 256, 256>>>(Wih_L, pWih_L, 512 * 128, 512 * 128);
    k_split<<<(512 * 64 + 255) / 256, 256>>>(Whh_L, pWhh_L, 512 * 64, 512 * 64);

    // ---- state init ----
    cudaMemcpyAsync(hC, hidden_C, sizeof(float) * NCLA * D, cudaMemcpyDeviceToDevice);
    cudaMemcpyAsync(hL, hidden_L, sizeof(float) * NLIT * D, cudaMemcpyDeviceToDevice);
    cudaMemsetAsync(phC, 0, sizeof(uint32_t) * 2 * PSC);   // split(0) == 0
    cudaMemsetAsync(phL, 0, sizeof(uint32_t) * 2 * PSL);
    k_split<<<(NLIT * 64 + 255) / 256, 256>>>(L_state, pL0, NLIT * 64, PSL);

    GSeg z = {nullptr, 0, nullptr, 0, 0};

    // ---- T message-passing rounds ----
    for (int r = 0; r < TSTEPS; r++) {
        uint32_t* pLcur  = (r & 1) ? pL1 : pL0;
        uint32_t* pLnext = (r & 1) ? pL0 : pL1;
        float* hOutFinal = (r == TSTEPS - 1) ? (float*)d_out : nullptr;

        // LC_pre = L @ W_lc^T + b_lc
        GSeg a1 = {pLcur, PSL, pW_lc, 64, 128 * 64};
        k_gemm_planes<<<dim3(D / 64, NLIT / 64), 256>>>(a1, z, z, b_lc, nullptr, LCpre, D);
        // LC_msgs = M^T @ LC_pre  (emits planes)
        k_spmm_split<<<NCLA / 4, 128>>>(ptrC, colC, LCpre, pCmsg, PSC);
        // C gates = Cmsg @ Wih_C^T + hC @ Whh_C^T + biases
        GSeg c1 = {pCmsg, PSC, pWih_C, 64, 512 * 64};
        GSeg c2 = {phC, PSC, pWhh_C, 64, 512 * 64};
        k_gemm_planes<<<dim3(4 * D / 64, NCLA / 64), 256>>>(c1, c2, z, bih_C, bhh_C,
                                                            gatesC, 4 * D);
        // C LSTM: h -> pCs planes, c -> hC fp32 + phC planes
        k_lstm_split<<<(NCLA * 64 + 255) / 256, 256>>>(gatesC, hC, nullptr,
                                                       pCs, PSC, phC, PSC, NCLA);
        // CL_pre = Cs @ W_cl^T + b_cl
        GSeg d1 = {pCs, PSC, pW_cl, 64, 128 * 64};
        k_gemm_planes<<<dim3(D / 64, NCLA / 64), 256>>>(d1, z, z, b_cl, nullptr, CLpre, D);
        // CL_msgs = M @ CL_pre  (emits planes)
        k_spmm_split<<<NLIT / 4, 128>>>(ptrL, colL, CLpre, pLmsg, PSL);
        // L gates = [Lmsg | Lcur] @ Wih_L^T + hL @ Whh_L^T + biases (concat fused)
        GSeg e1 = {pLmsg, PSL, pWih_L, 128, 512 * 128};
        GSeg e2 = {pLcur, PSL, pWih_L + 64, 128, 512 * 128};
        GSeg e3 = {phL, PSL, pWhh_L, 64, 512 * 64};
        k_gemm_planes<<<dim3(4 * D / 64, NLIT / 64), 256>>>(e1, e2, e3, bih_L, bhh_L,
                                                            gatesL, 4 * D);
        // L LSTM: h -> pLnext planes (+ d_out fp32 on last round), c -> hL + phL
        k_lstm_split<<<(NLIT * 64 + 255) / 256, 256>>>(gatesL, hL, hOutFinal,
                                                       pLnext, PSL, phL, PSL, NLIT);
    }
}